// round 1
// baseline (speedup 1.0000x reference)
#include <cuda_runtime.h>

// Problem constants: B=128, N=128, D=1024, H=8, HD=128, M = B*N = 16384
// Scratch: 8 x [B,H,N,HD] fp32 buffers (qw,kw,vw,qp,kp,qc,kc,att) = 512MB static.
#define MD_ELEMS (16384 * 1024)
__device__ float g_scratch[8ull * MD_ELEMS];

// ----------------------------------------------------------------------------
// Generic tiled SGEMM, C[16384,1024] = A[16384,1024(K)] * B[1024,1024] (+bias)
// Flexible A/C addressing:
//   A idx(r,k) = (r/128)*131072 + (k/128)*ACB + (r%128)*ARI + (k%128)
//   C idx(r,c) = (r/128)*131072 + (c/128)*CCB + (r%128)*CRI + (c%128)
// Row-major:   (ACB,ARI) = (128,1024)   / (CCB,CRI) = (128,1024)
// Head layout: (ACB,ARI) = (16384,128)  / (CCB,CRI) = (16384,128)
// ----------------------------------------------------------------------------
__global__ __launch_bounds__(256) void gemm128(
    const float* __restrict__ A, const float* __restrict__ Bm,
    float* __restrict__ C, const float* __restrict__ bias,
    int ACB, int ARI, int CCB, int CRI)
{
    const int rt = blockIdx.y;   // row tile (0..127)
    const int ct = blockIdx.x;   // col tile (0..7)
    const int tid = threadIdx.x;
    const int tx = tid & 15, ty = tid >> 4;

    __shared__ float As[16 * 132];   // A chunk transposed: As[kc][ri], pad 132
    __shared__ float Bs[16 * 128];   // B chunk: Bs[kc][ci]

    float acc[8][8];
#pragma unroll
    for (int i = 0; i < 8; i++)
#pragma unroll
        for (int j = 0; j < 8; j++) acc[i][j] = 0.f;

    const float* Arow = A + (long)rt * 131072;
    const float* Bcol = Bm + ct * 128;

    for (int kk = 0; kk < 1024; kk += 16) {
        const float* Abase = Arow + (kk >> 7) * ACB + (kk & 127);
        // A chunk: 128 rows x 16 cols -> transposed into As
#pragma unroll
        for (int p = 0; p < 2; p++) {
            int idx = tid + p * 256;         // 0..511
            int ri  = idx >> 2;              // 0..127
            int c4  = (idx & 3) * 4;         // 0,4,8,12
            float4 v = *(const float4*)(Abase + ri * ARI + c4);
            As[(c4 + 0) * 132 + ri] = v.x;
            As[(c4 + 1) * 132 + ri] = v.y;
            As[(c4 + 2) * 132 + ri] = v.z;
            As[(c4 + 3) * 132 + ri] = v.w;
        }
        // B chunk: 16 rows x 128 cols
#pragma unroll
        for (int p = 0; p < 2; p++) {
            int idx = tid + p * 256;
            int kc  = idx >> 5;              // 0..15
            int c4  = (idx & 31) * 4;        // 0..124
            *(float4*)&Bs[kc * 128 + c4] =
                *(const float4*)(Bcol + (kk + kc) * 1024 + c4);
        }
        __syncthreads();
#pragma unroll
        for (int kc = 0; kc < 16; kc++) {
            float a[8], b[8];
            *(float4*)(a)     = *(float4*)&As[kc * 132 + ty * 8];
            *(float4*)(a + 4) = *(float4*)&As[kc * 132 + ty * 8 + 4];
            *(float4*)(b)     = *(float4*)&Bs[kc * 128 + tx * 8];
            *(float4*)(b + 4) = *(float4*)&Bs[kc * 128 + tx * 8 + 4];
#pragma unroll
            for (int i = 0; i < 8; i++)
#pragma unroll
                for (int j = 0; j < 8; j++)
                    acc[i][j] += a[i] * b[j];
        }
        __syncthreads();
    }

    float* Cbase = C + (long)rt * 131072 + ct * CCB;
#pragma unroll
    for (int i = 0; i < 8; i++) {
        int ri = ty * 8 + i;
#pragma unroll
        for (int j = 0; j < 8; j += 4) {
            float4 v = *(float4*)&acc[i][j];
            if (bias) {
                int ci = ct * 128 + tx * 8 + j;
                v.x += bias[ci + 0];
                v.y += bias[ci + 1];
                v.z += bias[ci + 2];
                v.w += bias[ci + 3];
            }
            *(float4*)(Cbase + ri * CRI + tx * 8 + j) = v;
        }
    }
}

// ----------------------------------------------------------------------------
// Fused attention per (b,h): sim = Qw*Kw + Qp*Kp + Qc*Kc (all 128x128 plain
// matmuls, NOT transposed), scale, row-softmax, out = attn * V.
// One CTA per (b,h) block; 256 threads, 8x8 register tiles.
// ----------------------------------------------------------------------------
#define ATTN_SMEM ((128 * 132 + 16 * 132 + 16 * 128) * 4)

__global__ __launch_bounds__(256) void attn_kernel(
    const float* __restrict__ qw, const float* __restrict__ kw,
    const float* __restrict__ qp, const float* __restrict__ kp,
    const float* __restrict__ qc, const float* __restrict__ kcn,
    const float* __restrict__ vw, float* __restrict__ out)
{
    extern __shared__ float sm[];
    float* Atn = sm;                    // 128*132 : attn transposed [j][i]
    float* As  = sm + 128 * 132;        // 16*132  : q chunk transposed
    float* Bs  = As + 16 * 132;         // 16*128  : k/v chunk

    const int bh  = blockIdx.x;
    const long off = (long)bh * 16384;
    const int tid = threadIdx.x;
    const int tx = tid & 15, ty = tid >> 4;

    float acc[8][8];
#pragma unroll
    for (int i = 0; i < 8; i++)
#pragma unroll
        for (int j = 0; j < 8; j++) acc[i][j] = 0.f;

    const float* qs[3] = { qw + off, qp + off, qc + off };
    const float* ks[3] = { kw + off, kp + off, kcn + off };

    // ---- Phase 1: sim = sum of 3 streams ----
    for (int s = 0; s < 3; s++) {
        const float* q = qs[s];
        const float* k = ks[s];
        for (int kk = 0; kk < 128; kk += 16) {
#pragma unroll
            for (int p = 0; p < 2; p++) {
                int idx = tid + p * 256;
                int ri  = idx >> 2;
                int c4  = (idx & 3) * 4;
                float4 v = *(const float4*)(q + ri * 128 + kk + c4);
                As[(c4 + 0) * 132 + ri] = v.x;
                As[(c4 + 1) * 132 + ri] = v.y;
                As[(c4 + 2) * 132 + ri] = v.z;
                As[(c4 + 3) * 132 + ri] = v.w;
            }
#pragma unroll
            for (int p = 0; p < 2; p++) {
                int idx = tid + p * 256;
                int kc  = idx >> 5;
                int c4  = (idx & 31) * 4;
                *(float4*)&Bs[kc * 128 + c4] =
                    *(const float4*)(k + (kk + kc) * 128 + c4);
            }
            __syncthreads();
#pragma unroll
            for (int kc = 0; kc < 16; kc++) {
                float a[8], b[8];
                *(float4*)(a)     = *(float4*)&As[kc * 132 + ty * 8];
                *(float4*)(a + 4) = *(float4*)&As[kc * 132 + ty * 8 + 4];
                *(float4*)(b)     = *(float4*)&Bs[kc * 128 + tx * 8];
                *(float4*)(b + 4) = *(float4*)&Bs[kc * 128 + tx * 8 + 4];
#pragma unroll
                for (int i = 0; i < 8; i++)
#pragma unroll
                    for (int j = 0; j < 8; j++)
                        acc[i][j] += a[i] * b[j];
            }
            __syncthreads();
        }
    }

    // ---- Phase 2: scale + softmax over last axis (columns within a row) ----
    // Row i is owned by the 16 threads sharing ty (lanes form a 16-lane group).
    const float SC = 0.08838834764831845f;  // 128^-0.5
#pragma unroll
    for (int i = 0; i < 8; i++) {
        float m = -1e30f;
#pragma unroll
        for (int j = 0; j < 8; j++) { acc[i][j] *= SC; m = fmaxf(m, acc[i][j]); }
#pragma unroll
        for (int o = 8; o; o >>= 1) m = fmaxf(m, __shfl_xor_sync(0xffffffffu, m, o));
        float ssum = 0.f;
#pragma unroll
        for (int j = 0; j < 8; j++) { acc[i][j] = __expf(acc[i][j] - m); ssum += acc[i][j]; }
#pragma unroll
        for (int o = 8; o; o >>= 1) ssum += __shfl_xor_sync(0xffffffffu, ssum, o);
        float inv = 1.0f / ssum;
#pragma unroll
        for (int j = 0; j < 8; j++) acc[i][j] *= inv;
    }

    // store attn transposed (so phase 3 A-reads are conflict-friendly), reuse acc
#pragma unroll
    for (int i = 0; i < 8; i++)
#pragma unroll
        for (int j = 0; j < 8; j++) {
            Atn[(tx * 8 + j) * 132 + (ty * 8 + i)] = acc[i][j];
            acc[i][j] = 0.f;
        }
    __syncthreads();

    // ---- Phase 3: out = attn * V ----
    const float* v = vw + off;
    for (int kk = 0; kk < 128; kk += 16) {
#pragma unroll
        for (int p = 0; p < 2; p++) {
            int idx = tid + p * 256;
            int kc  = idx >> 5;
            int c4  = (idx & 31) * 4;
            *(float4*)&Bs[kc * 128 + c4] =
                *(const float4*)(v + (kk + kc) * 128 + c4);
        }
        __syncthreads();
#pragma unroll
        for (int kc = 0; kc < 16; kc++) {
            float a[8], b[8];
            *(float4*)(a)     = *(float4*)&Atn[(kk + kc) * 132 + ty * 8];
            *(float4*)(a + 4) = *(float4*)&Atn[(kk + kc) * 132 + ty * 8 + 4];
            *(float4*)(b)     = *(float4*)&Bs[kc * 128 + tx * 8];
            *(float4*)(b + 4) = *(float4*)&Bs[kc * 128 + tx * 8 + 4];
#pragma unroll
            for (int i = 0; i < 8; i++)
#pragma unroll
                for (int j = 0; j < 8; j++)
                    acc[i][j] += a[i] * b[j];
        }
        __syncthreads();
    }

#pragma unroll
    for (int i = 0; i < 8; i++) {
        int ri = ty * 8 + i;
#pragma unroll
        for (int j = 0; j < 8; j += 4)
            *(float4*)(out + off + ri * 128 + tx * 8 + j) = *(float4*)&acc[i][j];
    }
}

// ----------------------------------------------------------------------------
extern "C" void kernel_launch(void* const* d_in, const int* in_sizes, int n_in,
                              void* d_out, int out_size)
{
    (void)in_sizes; (void)n_in; (void)out_size;
    const float* words     = (const float*)d_in[0];
    const float* position  = (const float*)d_in[1];
    const float* conscious = (const float*)d_in[2];
    const float* Wq_w = (const float*)d_in[3];
    const float* Wk_w = (const float*)d_in[4];
    const float* Wv_w = (const float*)d_in[5];
    const float* Wq_p = (const float*)d_in[6];
    const float* Wk_p = (const float*)d_in[7];
    const float* Wq_c = (const float*)d_in[8];
    const float* Wk_c = (const float*)d_in[9];
    const float* Wo   = (const float*)d_in[10];
    const float* bo   = (const float*)d_in[11];
    float* out = (float*)d_out;

    void* symp = nullptr;
    cudaGetSymbolAddress(&symp, g_scratch);
    float* s   = (float*)symp;
    float* qw  = s + 0ull * MD_ELEMS;
    float* kw  = s + 1ull * MD_ELEMS;
    float* vw  = s + 2ull * MD_ELEMS;
    float* qp  = s + 3ull * MD_ELEMS;
    float* kp  = s + 4ull * MD_ELEMS;
    float* qc  = s + 5ull * MD_ELEMS;
    float* kc  = s + 6ull * MD_ELEMS;
    float* att = s + 7ull * MD_ELEMS;

    cudaFuncSetAttribute(attn_kernel,
                         cudaFuncAttributeMaxDynamicSharedMemorySize, ATTN_SMEM);

    dim3 grid(8, 128), blk(256);
    // Projections: row-major A (128,1024) -> head-layout C (16384,128)
    gemm128<<<grid, blk>>>(words,     Wq_w, qw, nullptr, 128, 1024, 16384, 128);
    gemm128<<<grid, blk>>>(words,     Wk_w, kw, nullptr, 128, 1024, 16384, 128);
    gemm128<<<grid, blk>>>(words,     Wv_w, vw, nullptr, 128, 1024, 16384, 128);
    gemm128<<<grid, blk>>>(position,  Wq_p, qp, nullptr, 128, 1024, 16384, 128);
    gemm128<<<grid, blk>>>(position,  Wk_p, kp, nullptr, 128, 1024, 16384, 128);
    gemm128<<<grid, blk>>>(conscious, Wq_c, qc, nullptr, 128, 1024, 16384, 128);
    gemm128<<<grid, blk>>>(conscious, Wk_c, kc, nullptr, 128, 1024, 16384, 128);

    // Fused 3-stream attention per (b,h)
    attn_kernel<<<1024, blk, ATTN_SMEM>>>(qw, kw, qp, kp, qc, kc, vw, att);

    // Final: head-layout A (16384,128) -> row-major C (128,1024), + bias
    gemm128<<<grid, blk>>>(att, Wo, out, bo, 16384, 128, 128, 1024);
}

// round 3
// speedup vs baseline: 2.4179x; 2.4179x over previous
#include <cuda_runtime.h>
#include <cuda_bf16.h>
#include <cstdint>

// Problem: B=128, N=128, D=1024, H=8, HD=128, M = B*N = 16384
#define MD_ELEMS (16384ull * 1024ull)
#define WT_ELEMS (1024ull * 1024ull)
__device__ float g_scratch[8ull * MD_ELEMS + 8ull * WT_ELEMS];

__device__ __forceinline__ uint32_t s2u(const void* p) {
    uint32_t a;
    asm("{ .reg .u64 t; cvta.to.shared.u64 t, %1; cvt.u32.u64 %0, t; }"
        : "=r"(a) : "l"(p));
    return a;
}
__device__ __forceinline__ void ldsm4(uint32_t* r, uint32_t addr) {
    asm volatile("ldmatrix.sync.aligned.m8n8.x4.shared.b16 {%0,%1,%2,%3}, [%4];"
                 : "=r"(r[0]), "=r"(r[1]), "=r"(r[2]), "=r"(r[3]) : "r"(addr));
}
__device__ __forceinline__ void mma_bf16(float* d, const uint32_t* a, const uint32_t* b) {
    asm volatile(
        "mma.sync.aligned.m16n8k16.row.col.f32.bf16.bf16.f32 "
        "{%0,%1,%2,%3},{%4,%5,%6,%7},{%8,%9},{%0,%1,%2,%3};"
        : "+f"(d[0]), "+f"(d[1]), "+f"(d[2]), "+f"(d[3])
        : "r"(a[0]), "r"(a[1]), "r"(a[2]), "r"(a[3]), "r"(b[0]), "r"(b[1]));
}

struct alignas(8) BF4 { __nv_bfloat16 a, b, c, d; };

// ======================= Weight transpose =====================================
__global__ __launch_bounds__(256) void transpose_w(
    const float* __restrict__ src, float* __restrict__ dst)
{
    __shared__ float t[32][33];
    int bx = blockIdx.x * 32, by = blockIdx.y * 32;
    int tx = threadIdx.x, ty = threadIdx.y;
#pragma unroll
    for (int i = ty; i < 32; i += 8)
        t[i][tx] = src[(size_t)(by + i) * 1024 + bx + tx];
    __syncthreads();
#pragma unroll
    for (int i = ty; i < 32; i += 8)
        dst[(size_t)(bx + i) * 1024 + by + tx] = t[tx][i];
}

// ======================= bf16-split mma.sync GEMM =============================
// C[16384,1024] = A[16384,1024] * WT^T   (WT is [N,K] row-major)
// Flexible A/C addressing:
//   A idx(r,k) = (r/128)*131072 + (k/128)*ACB + (r%128)*ARI + (k%128)
//   C idx(r,c) = (r/128)*131072 + (c/128)*CCB + (r%128)*CRI + (c%128)
// Smem per buffer (bytes): AH@0, AL@6144, BH@12288, BL@18432; buf stride 24576.
// Rows: 128 x 16 bf16 (32B data) padded to 48B stride (ldmatrix conflict-free).
__global__ __launch_bounds__(256) void gemm_mma(
    const float* __restrict__ A, const float* __restrict__ WT,
    float* __restrict__ C, const float* __restrict__ bias,
    int ACB, int ARI, int CCB, int CRI)
{
    __shared__ char smem[49152];
    const uint32_t sb = s2u(smem);
    const int tid = threadIdx.x;
    const int lane = tid & 31, wid = tid >> 5;
    const int rt = blockIdx.y, ct = blockIdx.x;
    const int wm = wid & 1;        // M band (64 rows)
    const int wn = wid >> 1;       // N band (32 cols)
    const int s8 = lane >> 3, r8 = lane & 7;
    const uint32_t aLane = (uint32_t)(((s8 & 1) * 8 + r8) * 48 + (s8 >> 1) * 16);
    const uint32_t bLane = (uint32_t)(((s8 >> 1) * 8 + r8) * 48 + (s8 & 1) * 16);

    float acc[4][4][4];
#pragma unroll
    for (int i = 0; i < 4; i++)
#pragma unroll
        for (int j = 0; j < 4; j++)
#pragma unroll
            for (int k = 0; k < 4; k++) acc[i][j][k] = 0.f;

    const int vrow = tid >> 2, vk4 = (tid & 3) * 4;   // loader mapping (p adds 64 rows)

    auto ldg = [&](int c, float4* ra, float4* rb) {
        const int kk = c * 16;
        const float* Ab = A + (size_t)rt * 131072 + (size_t)(kk >> 7) * ACB + (kk & 127);
        const float* Bb = WT + (size_t)(ct * 128) * 1024 + kk;
#pragma unroll
        for (int p = 0; p < 2; p++) {
            int row = vrow + p * 64;
            ra[p] = *(const float4*)(Ab + (size_t)row * ARI + vk4);
            rb[p] = *(const float4*)(Bb + (size_t)row * 1024 + vk4);
        }
    };
    auto split4 = [](float4 v, BF4& h, BF4& l) {
        h.a = __float2bfloat16(v.x); l.a = __float2bfloat16(v.x - __bfloat162float(h.a));
        h.b = __float2bfloat16(v.y); l.b = __float2bfloat16(v.y - __bfloat162float(h.b));
        h.c = __float2bfloat16(v.z); l.c = __float2bfloat16(v.z - __bfloat162float(h.c));
        h.d = __float2bfloat16(v.w); l.d = __float2bfloat16(v.w - __bfloat162float(h.d));
    };
    auto sts = [&](int bu, const float4* ra, const float4* rb) {
        char* base = smem + bu * 24576;
#pragma unroll
        for (int p = 0; p < 2; p++) {
            int row = vrow + p * 64;
            uint32_t off = (uint32_t)(row * 48 + vk4 * 2);
            BF4 h, l;
            split4(ra[p], h, l);
            *(BF4*)(base + off)         = h;
            *(BF4*)(base + 6144 + off)  = l;
            split4(rb[p], h, l);
            *(BF4*)(base + 12288 + off) = h;
            *(BF4*)(base + 18432 + off) = l;
        }
    };

    float4 ra[2], rb[2];
    ldg(0, ra, rb);
    sts(0, ra, rb);
    ldg(1, ra, rb);
    __syncthreads();

    for (int c = 0; c < 64; c++) {
        const int bu = c & 1;
        if (c + 1 < 64) sts(bu ^ 1, ra, rb);
        if (c + 2 < 64) ldg(c + 2, ra, rb);

        // ---- compute chunk from buffer bu ----
        const uint32_t off = sb + (uint32_t)(bu * 24576);
        uint32_t ah[4][4], bh[4][2], bl[4][2];
#pragma unroll
        for (int mt = 0; mt < 4; mt++)
            ldsm4(ah[mt], off + (uint32_t)((wm * 64 + mt * 16) * 48) + aLane);
#pragma unroll
        for (int g = 0; g < 2; g++) {
            uint32_t q[4];
            ldsm4(q, off + 12288u + (uint32_t)((wn * 32 + g * 16) * 48) + bLane);
            bh[g * 2][0] = q[0]; bh[g * 2][1] = q[1];
            bh[g * 2 + 1][0] = q[2]; bh[g * 2 + 1][1] = q[3];
            ldsm4(q, off + 18432u + (uint32_t)((wn * 32 + g * 16) * 48) + bLane);
            bl[g * 2][0] = q[0]; bl[g * 2][1] = q[1];
            bl[g * 2 + 1][0] = q[2]; bl[g * 2 + 1][1] = q[3];
        }
#pragma unroll
        for (int mt = 0; mt < 4; mt++)
#pragma unroll
            for (int nt = 0; nt < 4; nt++) {
                mma_bf16(acc[mt][nt], ah[mt], bh[nt]);
                mma_bf16(acc[mt][nt], ah[mt], bl[nt]);
            }
#pragma unroll
        for (int mt = 0; mt < 4; mt++) {
            uint32_t al[4];
            ldsm4(al, off + 6144u + (uint32_t)((wm * 64 + mt * 16) * 48) + aLane);
#pragma unroll
            for (int nt = 0; nt < 4; nt++)
                mma_bf16(acc[mt][nt], al, bh[nt]);
        }
        __syncthreads();
    }

    // ---- epilogue ----
    const int g = lane >> 2, cp = (lane & 3) * 2;
    float* Cb = C + (size_t)rt * 131072 + (size_t)ct * CCB;
#pragma unroll
    for (int mt = 0; mt < 4; mt++) {
#pragma unroll
        for (int nt = 0; nt < 4; nt++) {
            int row = wm * 64 + mt * 16 + g;
            int col = wn * 32 + nt * 8 + cp;
            float2 v0 = { acc[mt][nt][0], acc[mt][nt][1] };
            float2 v1 = { acc[mt][nt][2], acc[mt][nt][3] };
            if (bias) {
                float b0 = bias[ct * 128 + col], b1 = bias[ct * 128 + col + 1];
                v0.x += b0; v0.y += b1; v1.x += b0; v1.y += b1;
            }
            *(float2*)(Cb + (size_t)row * CRI + col) = v0;
            *(float2*)(Cb + (size_t)(row + 8) * CRI + col) = v1;
        }
    }
}

// ======================= Fused FFMA attention (validated) =====================
#define ATTN_SMEM ((128 * 132 + 16 * 132 + 16 * 128) * 4)

__global__ __launch_bounds__(256) void attn_kernel(
    const float* __restrict__ qw, const float* __restrict__ kw,
    const float* __restrict__ qp, const float* __restrict__ kp,
    const float* __restrict__ qc, const float* __restrict__ kcn,
    const float* __restrict__ vw, float* __restrict__ out)
{
    extern __shared__ float smf[];
    float* Atn = smf;
    float* As  = smf + 128 * 132;
    float* Bs  = As + 16 * 132;

    const int bh  = blockIdx.x;
    const long off = (long)bh * 16384;
    const int tid = threadIdx.x;
    const int tx = tid & 15, ty = tid >> 4;

    float acc[8][8];
#pragma unroll
    for (int i = 0; i < 8; i++)
#pragma unroll
        for (int j = 0; j < 8; j++) acc[i][j] = 0.f;

    const float* qs[3] = { qw + off, qp + off, qc + off };
    const float* ks[3] = { kw + off, kp + off, kcn + off };

    for (int s = 0; s < 3; s++) {
        const float* q = qs[s];
        const float* k = ks[s];
        for (int kk = 0; kk < 128; kk += 16) {
#pragma unroll
            for (int p = 0; p < 2; p++) {
                int idx = tid + p * 256;
                int ri  = idx >> 2;
                int c4  = (idx & 3) * 4;
                float4 v = *(const float4*)(q + ri * 128 + kk + c4);
                As[(c4 + 0) * 132 + ri] = v.x;
                As[(c4 + 1) * 132 + ri] = v.y;
                As[(c4 + 2) * 132 + ri] = v.z;
                As[(c4 + 3) * 132 + ri] = v.w;
            }
#pragma unroll
            for (int p = 0; p < 2; p++) {
                int idx = tid + p * 256;
                int kc  = idx >> 5;
                int c4  = (idx & 31) * 4;
                *(float4*)&Bs[kc * 128 + c4] =
                    *(const float4*)(k + (kk + kc) * 128 + c4);
            }
            __syncthreads();
#pragma unroll
            for (int kc = 0; kc < 16; kc++) {
                float a[8], b[8];
                *(float4*)(a)     = *(float4*)&As[kc * 132 + ty * 8];
                *(float4*)(a + 4) = *(float4*)&As[kc * 132 + ty * 8 + 4];
                *(float4*)(b)     = *(float4*)&Bs[kc * 128 + tx * 8];
                *(float4*)(b + 4) = *(float4*)&Bs[kc * 128 + tx * 8 + 4];
#pragma unroll
                for (int i = 0; i < 8; i++)
#pragma unroll
                    for (int j = 0; j < 8; j++)
                        acc[i][j] += a[i] * b[j];
            }
            __syncthreads();
        }
    }

    const float SC = 0.08838834764831845f;
#pragma unroll
    for (int i = 0; i < 8; i++) {
        float m = -1e30f;
#pragma unroll
        for (int j = 0; j < 8; j++) { acc[i][j] *= SC; m = fmaxf(m, acc[i][j]); }
#pragma unroll
        for (int o = 8; o; o >>= 1) m = fmaxf(m, __shfl_xor_sync(0xffffffffu, m, o));
        float ssum = 0.f;
#pragma unroll
        for (int j = 0; j < 8; j++) { acc[i][j] = __expf(acc[i][j] - m); ssum += acc[i][j]; }
#pragma unroll
        for (int o = 8; o; o >>= 1) ssum += __shfl_xor_sync(0xffffffffu, ssum, o);
        float inv = 1.0f / ssum;
#pragma unroll
        for (int j = 0; j < 8; j++) acc[i][j] *= inv;
    }

#pragma unroll
    for (int i = 0; i < 8; i++)
#pragma unroll
        for (int j = 0; j < 8; j++) {
            Atn[(tx * 8 + j) * 132 + (ty * 8 + i)] = acc[i][j];
            acc[i][j] = 0.f;
        }
    __syncthreads();

    const float* v = vw + off;
    for (int kk = 0; kk < 128; kk += 16) {
#pragma unroll
        for (int p = 0; p < 2; p++) {
            int idx = tid + p * 256;
            int kc  = idx >> 5;
            int c4  = (idx & 31) * 4;
            *(float4*)&Bs[kc * 128 + c4] =
                *(const float4*)(v + (kk + kc) * 128 + c4);
        }
        __syncthreads();
#pragma unroll
        for (int kc = 0; kc < 16; kc++) {
            float a[8], b[8];
            *(float4*)(a)     = *(float4*)&Atn[(kk + kc) * 132 + ty * 8];
            *(float4*)(a + 4) = *(float4*)&Atn[(kk + kc) * 132 + ty * 8 + 4];
            *(float4*)(b)     = *(float4*)&Bs[kc * 128 + tx * 8];
            *(float4*)(b + 4) = *(float4*)&Bs[kc * 128 + tx * 8 + 4];
#pragma unroll
            for (int i = 0; i < 8; i++)
#pragma unroll
                for (int j = 0; j < 8; j++)
                    acc[i][j] += a[i] * b[j];
        }
        __syncthreads();
    }

#pragma unroll
    for (int i = 0; i < 8; i++) {
        int ri = ty * 8 + i;
#pragma unroll
        for (int j = 0; j < 8; j += 4)
            *(float4*)(out + off + ri * 128 + tx * 8 + j) = *(float4*)&acc[i][j];
    }
}

// ======================= launch ==============================================
extern "C" void kernel_launch(void* const* d_in, const int* in_sizes, int n_in,
                              void* d_out, int out_size)
{
    (void)in_sizes; (void)n_in; (void)out_size;
    const float* words     = (const float*)d_in[0];
    const float* position  = (const float*)d_in[1];
    const float* conscious = (const float*)d_in[2];
    const float* W[8] = { (const float*)d_in[3], (const float*)d_in[4],
                          (const float*)d_in[5], (const float*)d_in[6],
                          (const float*)d_in[7], (const float*)d_in[8],
                          (const float*)d_in[9], (const float*)d_in[10] };
    const float* bo = (const float*)d_in[11];
    float* out = (float*)d_out;

    void* symp = nullptr;
    cudaGetSymbolAddress(&symp, g_scratch);
    float* s   = (float*)symp;
    float* qw  = s + 0ull * MD_ELEMS;
    float* kw  = s + 1ull * MD_ELEMS;
    float* vw  = s + 2ull * MD_ELEMS;
    float* qp  = s + 3ull * MD_ELEMS;
    float* kp  = s + 4ull * MD_ELEMS;
    float* qc  = s + 5ull * MD_ELEMS;
    float* kc  = s + 6ull * MD_ELEMS;
    float* att = s + 7ull * MD_ELEMS;
    float* wt  = s + 8ull * MD_ELEMS;

    cudaFuncSetAttribute(attn_kernel, cudaFuncAttributeMaxDynamicSharedMemorySize, ATTN_SMEM);

    // 1) transpose weights: wt[i] = W[i]^T  ([N,K] row-major)
    dim3 tgrid(32, 32), tblk(32, 8);
    for (int i = 0; i < 8; i++)
        transpose_w<<<tgrid, tblk>>>(W[i], wt + (size_t)i * WT_ELEMS);

    // 2) projections: row-major A -> head-layout C
    dim3 ggrid(8, 128), gblk(256);
    float* outs[7] = { qw, kw, vw, qp, kp, qc, kc };
    const float* ins[7] = { words, words, words, position, position, conscious, conscious };
    for (int i = 0; i < 7; i++)
        gemm_mma<<<ggrid, gblk>>>(ins[i], wt + (size_t)i * WT_ELEMS,
                                  outs[i], nullptr, 128, 1024, 16384, 128);

    // 3) fused 3-stream attention per (b,h)
    attn_kernel<<<1024, gblk, ATTN_SMEM>>>(qw, kw, qp, kp, qc, kc, vw, att);

    // 4) final: head-layout A -> row-major C, + bias
    gemm_mma<<<ggrid, gblk>>>(att, wt + 7ull * WT_ELEMS,
                              out, bo, 16384, 128, 128, 1024);
}

// round 4
// speedup vs baseline: 2.4267x; 1.0036x over previous
#include <cuda_runtime.h>
#include <cuda_bf16.h>
#include <cstdint>

// Problem: B=128, N=128, D=1024, H=8, HD=128, M = B*N = 16384
#define PLANE  (16384ull * 1024ull)     // activation plane elems (bf16)
#define WPLANE (1024ull * 1024ull)      // weight plane elems (bf16)
// planes: 0-5 inputs (w,p,c × h/l), 6-19 q/k/v streams, 20-21 att, then weights
__device__ __align__(1024) __nv_bfloat16 g_bf[22ull * PLANE + 16ull * WPLANE];

typedef __nv_bfloat16 bf16;

// ======================= PTX helpers =========================================
__device__ __forceinline__ uint32_t s2u(const void* p) {
    uint32_t a;
    asm("{ .reg .u64 t; cvta.to.shared.u64 t, %1; cvt.u32.u64 %0, t; }"
        : "=r"(a) : "l"(p));
    return a;
}
__device__ __forceinline__ void ldsm4(uint32_t* r, uint32_t addr) {
    asm volatile("ldmatrix.sync.aligned.m8n8.x4.shared.b16 {%0,%1,%2,%3}, [%4];"
                 : "=r"(r[0]), "=r"(r[1]), "=r"(r[2]), "=r"(r[3]) : "r"(addr));
}
__device__ __forceinline__ void ldsm4t(uint32_t* r, uint32_t addr) {
    asm volatile("ldmatrix.sync.aligned.m8n8.x4.trans.shared.b16 {%0,%1,%2,%3}, [%4];"
                 : "=r"(r[0]), "=r"(r[1]), "=r"(r[2]), "=r"(r[3]) : "r"(addr));
}
__device__ __forceinline__ void mma_bf16(float* d, const uint32_t* a, const uint32_t* b) {
    asm volatile(
        "mma.sync.aligned.m16n8k16.row.col.f32.bf16.bf16.f32 "
        "{%0,%1,%2,%3},{%4,%5,%6,%7},{%8,%9},{%0,%1,%2,%3};"
        : "+f"(d[0]), "+f"(d[1]), "+f"(d[2]), "+f"(d[3])
        : "r"(a[0]), "r"(a[1]), "r"(a[2]), "r"(a[3]), "r"(b[0]), "r"(b[1]));
}
#define CP16(dst, src) \
    asm volatile("cp.async.cg.shared.global [%0], [%1], 16;" :: "r"(dst), "l"(src))
#define CPCOMMIT() asm volatile("cp.async.commit_group;" ::: "memory")
#define CPWAIT2()  asm volatile("cp.async.wait_group 2;" ::: "memory")
#define CPWAIT0()  asm volatile("cp.async.wait_group 0;" ::: "memory")

__device__ __forceinline__ void split1(float v, bf16& h, bf16& l) {
    h = __float2bfloat16(v);
    l = __float2bfloat16(v - __bfloat162float(h));
}

// ======================= input split =========================================
__global__ __launch_bounds__(256) void split_input(
    const float* __restrict__ src, bf16* __restrict__ h, bf16* __restrict__ l)
{
    size_t i4 = ((size_t)blockIdx.x * 256 + threadIdx.x) * 4;
    float4 v = *(const float4*)(src + i4);
    bf16 h0, l0, h1, l1, h2, l2, h3, l3;
    split1(v.x, h0, l0); split1(v.y, h1, l1);
    split1(v.z, h2, l2); split1(v.w, h3, l3);
    __nv_bfloat162 hh0; hh0.x = h0; hh0.y = h1;
    __nv_bfloat162 hh1; hh1.x = h2; hh1.y = h3;
    __nv_bfloat162 ll0; ll0.x = l0; ll0.y = l1;
    __nv_bfloat162 ll1; ll1.x = l2; ll1.y = l3;
    *(__nv_bfloat162*)(h + i4)     = hh0;
    *(__nv_bfloat162*)(h + i4 + 2) = hh1;
    *(__nv_bfloat162*)(l + i4)     = ll0;
    *(__nv_bfloat162*)(l + i4 + 2) = ll1;
}

// ======================= weight transpose + split ============================
__global__ __launch_bounds__(256) void transpose_w_split(
    const float* __restrict__ src, bf16* __restrict__ h, bf16* __restrict__ l)
{
    __shared__ float t[32][33];
    int bx = blockIdx.x * 32, by = blockIdx.y * 32;
    int tx = threadIdx.x, ty = threadIdx.y;
#pragma unroll
    for (int i = ty; i < 32; i += 8)
        t[i][tx] = src[(size_t)(by + i) * 1024 + bx + tx];
    __syncthreads();
#pragma unroll
    for (int i = ty; i < 32; i += 8) {
        bf16 hh, ll;
        split1(t[tx][i], hh, ll);
        size_t o = (size_t)(bx + i) * 1024 + by + tx;
        h[o] = hh; l[o] = ll;
    }
}

// ======================= bf16-split mma.sync GEMM (cp.async, 4-stage) ========
// C[16384,1024] = A * B^T, all operands pre-split bf16 hi/lo planes.
// A idx(r,k) = (r/128)*131072 + (k/128)*ACB + (r%128)*ARI + (k%128)
// C idx(r,c) = (r/128)*131072 + (c/128)*CCB + (r%128)*CRI + (c%128)
// Stage layout (bytes): Ah@0 Al@6144 Bh@12288 Bl@18432, stage stride 24576.
#define GEMM_SMEM (4 * 24576)

__global__ __launch_bounds__(256, 2) void gemm_bf(
    const bf16* __restrict__ Ah, const bf16* __restrict__ Al,
    const bf16* __restrict__ Bh, const bf16* __restrict__ Bl,
    float* __restrict__ Cf, bf16* __restrict__ Ch, bf16* __restrict__ Cl,
    const float* __restrict__ bias, int ACB, int ARI, int CCB, int CRI)
{
    extern __shared__ __align__(1024) char smem[];
    const uint32_t sb = s2u(smem);
    const int tid = threadIdx.x;
    const int lane = tid & 31, wid = tid >> 5;
    const int rt = blockIdx.y, ct = blockIdx.x;
    const int wm = wid & 1, wn = wid >> 1;
    const int s8 = lane >> 3, r8 = lane & 7;
    const uint32_t aLane = (uint32_t)(((s8 & 1) * 8 + r8) * 48 + (s8 >> 1) * 16);
    const uint32_t bLane = (uint32_t)(((s8 >> 1) * 8 + r8) * 48 + (s8 & 1) * 16);

    const int row = tid >> 1, half = tid & 1;
    const size_t aoff = (size_t)rt * 131072 + (size_t)row * ARI + half * 8;
    const size_t boff = (size_t)(ct * 128 + row) * 1024 + half * 8;
    const uint32_t dstoff = (uint32_t)(row * 48 + half * 16);

    float acc[4][4][4];
#pragma unroll
    for (int i = 0; i < 4; i++)
#pragma unroll
        for (int j = 0; j < 4; j++)
#pragma unroll
            for (int k = 0; k < 4; k++) acc[i][j][k] = 0.f;

    auto load_chunk = [&](int c) {
        const int kk = c * 16;
        const uint32_t st = sb + (uint32_t)((c & 3) * 24576) + dstoff;
        const size_t asrc = aoff + (size_t)(kk >> 7) * ACB + (kk & 127);
        const size_t bsrc = boff + kk;
        CP16(st,          Ah + asrc);
        CP16(st + 6144,   Al + asrc);
        CP16(st + 12288,  Bh + bsrc);
        CP16(st + 18432,  Bl + bsrc);
    };

    load_chunk(0); CPCOMMIT();
    load_chunk(1); CPCOMMIT();
    load_chunk(2); CPCOMMIT();

    for (int c = 0; c < 64; c++) {
        CPWAIT2();
        __syncthreads();
        if (c + 3 < 64) load_chunk(c + 3);
        CPCOMMIT();

        const uint32_t off = sb + (uint32_t)((c & 3) * 24576);
        uint32_t ah[4][4], bh[4][2], bl[4][2];
#pragma unroll
        for (int mt = 0; mt < 4; mt++)
            ldsm4(ah[mt], off + (uint32_t)((wm * 64 + mt * 16) * 48) + aLane);
#pragma unroll
        for (int g = 0; g < 2; g++) {
            uint32_t q[4];
            ldsm4(q, off + 12288u + (uint32_t)((wn * 32 + g * 16) * 48) + bLane);
            bh[g * 2][0] = q[0]; bh[g * 2][1] = q[1];
            bh[g * 2 + 1][0] = q[2]; bh[g * 2 + 1][1] = q[3];
            ldsm4(q, off + 18432u + (uint32_t)((wn * 32 + g * 16) * 48) + bLane);
            bl[g * 2][0] = q[0]; bl[g * 2][1] = q[1];
            bl[g * 2 + 1][0] = q[2]; bl[g * 2 + 1][1] = q[3];
        }
#pragma unroll
        for (int mt = 0; mt < 4; mt++)
#pragma unroll
            for (int nt = 0; nt < 4; nt++) {
                mma_bf16(acc[mt][nt], ah[mt], bh[nt]);
                mma_bf16(acc[mt][nt], ah[mt], bl[nt]);
            }
#pragma unroll
        for (int mt = 0; mt < 4; mt++) {
            uint32_t al[4];
            ldsm4(al, off + 6144u + (uint32_t)((wm * 64 + mt * 16) * 48) + aLane);
#pragma unroll
            for (int nt = 0; nt < 4; nt++)
                mma_bf16(acc[mt][nt], al, bh[nt]);
        }
    }

    // ---- epilogue ----
    const int g = lane >> 2, cp = (lane & 3) * 2;
    const size_t cbase = (size_t)rt * 131072 + (size_t)ct * CCB;
#pragma unroll
    for (int mt = 0; mt < 4; mt++) {
#pragma unroll
        for (int nt = 0; nt < 4; nt++) {
            int r0 = wm * 64 + mt * 16 + g;
            int col = wn * 32 + nt * 8 + cp;
            float v0 = acc[mt][nt][0], v1 = acc[mt][nt][1];
            float v2 = acc[mt][nt][2], v3 = acc[mt][nt][3];
            size_t o0 = cbase + (size_t)r0 * CRI + col;
            size_t o1 = cbase + (size_t)(r0 + 8) * CRI + col;
            if (Cf) {
                float b0 = bias[ct * 128 + col], b1 = bias[ct * 128 + col + 1];
                *(float2*)(Cf + o0) = make_float2(v0 + b0, v1 + b1);
                *(float2*)(Cf + o1) = make_float2(v2 + b0, v3 + b1);
            } else {
                bf16 h0, l0, h1, l1;
                split1(v0, h0, l0); split1(v1, h1, l1);
                __nv_bfloat162 hh; hh.x = h0; hh.y = h1;
                __nv_bfloat162 ll; ll.x = l0; ll.y = l1;
                *(__nv_bfloat162*)(Ch + o0) = hh;
                *(__nv_bfloat162*)(Cl + o0) = ll;
                split1(v2, h0, l0); split1(v3, h1, l1);
                hh.x = h0; hh.y = h1; ll.x = l0; ll.y = l1;
                *(__nv_bfloat162*)(Ch + o1) = hh;
                *(__nv_bfloat162*)(Cl + o1) = ll;
            }
        }
    }
}

// ======================= mma attention =======================================
// One CTA per (b,h). warp w owns rows w*16..w*16+15 (full 128 cols).
// sim = sum_s Q_s (128x128) * K_s (128x128), softmax rows, out = P * V.
// smem: P_h@0 (128x272B), P_l@34816, Q stages@69632 (4x12288: h@0,l@6144),
//       K/V stages@118784 (4x8704: h@0,l@4352). total 153600.
#define ATT_SMEM 153600
#define ATT_P_L   34816u
#define ATT_QST   69632u
#define ATT_KST   118784u

__global__ __launch_bounds__(256, 1) void attn_mma(
    const bf16* __restrict__ qwh, const bf16* __restrict__ qwl,
    const bf16* __restrict__ kwh, const bf16* __restrict__ kwl,
    const bf16* __restrict__ qph, const bf16* __restrict__ qpl,
    const bf16* __restrict__ kph, const bf16* __restrict__ kpl,
    const bf16* __restrict__ qch, const bf16* __restrict__ qcl,
    const bf16* __restrict__ kch, const bf16* __restrict__ kcl,
    const bf16* __restrict__ vh,  const bf16* __restrict__ vl,
    bf16* __restrict__ ath, bf16* __restrict__ atl)
{
    extern __shared__ __align__(1024) char smem[];
    const uint32_t sb = s2u(smem);
    const int tid = threadIdx.x;
    const int lane = tid & 31, w = tid >> 5;
    const size_t bhoff = (size_t)blockIdx.x * 16384;

    const bf16* QH[3] = { qwh + bhoff, qph + bhoff, qch + bhoff };
    const bf16* QL[3] = { qwl + bhoff, qpl + bhoff, qcl + bhoff };
    const bf16* KH[3] = { kwh + bhoff, kph + bhoff, kch + bhoff };
    const bf16* KL[3] = { kwl + bhoff, kpl + bhoff, kcl + bhoff };

    const int s8 = lane >> 3, r8 = lane & 7;
    const uint32_t aLane = (uint32_t)(((s8 & 1) * 8 + r8) * 48 + (s8 >> 1) * 16);
    const uint32_t aPL   = (uint32_t)(((s8 & 1) * 8 + r8) * 272 + (s8 >> 1) * 16);
    const uint32_t kr = (uint32_t)(lane & 15);        // trans-ldmatrix row
    const uint32_t nf = (uint32_t)((lane >> 4) * 8);  // trans-ldmatrix n-half
    const uint32_t wrow48  = (uint32_t)(w * 16 * 48);
    const uint32_t wrow272 = (uint32_t)(w * 16 * 272);

    // loader thread mappings
    const int qrow = tid >> 1, qhalf = tid & 1;
    const uint32_t qdst = (uint32_t)(qrow * 48 + qhalf * 16);
    const int krow = tid >> 4, kseg = tid & 15;
    const uint32_t kdst = (uint32_t)(krow * 272 + kseg * 16);

    auto loadQK = [&](int it) {
        int s = it >> 3, c = it & 7;
        uint32_t qs = sb + ATT_QST + (uint32_t)((it & 3) * 12288) + qdst;
        size_t qsrc = (size_t)qrow * 128 + c * 16 + qhalf * 8;
        CP16(qs,        QH[s] + qsrc);
        CP16(qs + 6144, QL[s] + qsrc);
        uint32_t ks = sb + ATT_KST + (uint32_t)((it & 3) * 8704) + kdst;
        size_t ksrc = (size_t)(c * 16 + krow) * 128 + kseg * 8;
        CP16(ks,        KH[s] + ksrc);
        CP16(ks + 4352, KL[s] + ksrc);
    };
    auto loadV = [&](int v) {
        uint32_t ks = sb + ATT_KST + (uint32_t)((v & 3) * 8704) + kdst;
        size_t ksrc = bhoff + (size_t)(v * 16 + krow) * 128 + kseg * 8;
        CP16(ks,        vh + ksrc);
        CP16(ks + 4352, vl + ksrc);
    };

    float acc[16][4];
#pragma unroll
    for (int i = 0; i < 16; i++)
#pragma unroll
        for (int j = 0; j < 4; j++) acc[i][j] = 0.f;

    loadQK(0); CPCOMMIT();
    loadQK(1); CPCOMMIT();
    loadQK(2); CPCOMMIT();

    // ---- Phase 1: sim (24 iters = 3 streams x 8 k-chunks) ----
    for (int it = 0; it < 24; it++) {
        CPWAIT2();
        __syncthreads();
        if (it + 3 < 24) loadQK(it + 3);
        CPCOMMIT();

        const uint32_t qs = sb + ATT_QST + (uint32_t)((it & 3) * 12288);
        const uint32_t ks = sb + ATT_KST + (uint32_t)((it & 3) * 8704);
        uint32_t ah[4], al[4];
        ldsm4(ah, qs + wrow48 + aLane);
        ldsm4(al, qs + 6144 + wrow48 + aLane);
#pragma unroll
        for (int g = 0; g < 8; g++) {
            uint32_t bh[4], bl[4];
            uint32_t baddr = ks + kr * 272 + (g * 16 + nf) * 2;
            ldsm4t(bh, baddr);
            ldsm4t(bl, baddr + 4352);
            mma_bf16(acc[2 * g],     ah, bh);
            mma_bf16(acc[2 * g],     ah, bl);
            mma_bf16(acc[2 * g],     al, bh);
            mma_bf16(acc[2 * g + 1], ah, bh + 2);
            mma_bf16(acc[2 * g + 1], ah, bl + 2);
            mma_bf16(acc[2 * g + 1], al, bh + 2);
        }
    }

    // prefetch V chunks 0..2 (stages 0..2 are free; overlap with softmax)
    loadV(0); CPCOMMIT();
    loadV(1); CPCOMMIT();
    loadV(2); CPCOMMIT();

    // ---- Phase 2: softmax (warp-local; rows g and g+8 per lane) ----
    const float SC = 0.08838834764831845f;   // 128^-0.5
    float m0 = -1e30f, m1 = -1e30f;
#pragma unroll
    for (int nt = 0; nt < 16; nt++) {
#pragma unroll
        for (int j = 0; j < 4; j++) acc[nt][j] *= SC;
        m0 = fmaxf(m0, fmaxf(acc[nt][0], acc[nt][1]));
        m1 = fmaxf(m1, fmaxf(acc[nt][2], acc[nt][3]));
    }
    m0 = fmaxf(m0, __shfl_xor_sync(0xffffffffu, m0, 1));
    m0 = fmaxf(m0, __shfl_xor_sync(0xffffffffu, m0, 2));
    m1 = fmaxf(m1, __shfl_xor_sync(0xffffffffu, m1, 1));
    m1 = fmaxf(m1, __shfl_xor_sync(0xffffffffu, m1, 2));
    float sum0 = 0.f, sum1 = 0.f;
#pragma unroll
    for (int nt = 0; nt < 16; nt++) {
        acc[nt][0] = __expf(acc[nt][0] - m0); sum0 += acc[nt][0];
        acc[nt][1] = __expf(acc[nt][1] - m0); sum0 += acc[nt][1];
        acc[nt][2] = __expf(acc[nt][2] - m1); sum1 += acc[nt][2];
        acc[nt][3] = __expf(acc[nt][3] - m1); sum1 += acc[nt][3];
    }
    sum0 += __shfl_xor_sync(0xffffffffu, sum0, 1);
    sum0 += __shfl_xor_sync(0xffffffffu, sum0, 2);
    sum1 += __shfl_xor_sync(0xffffffffu, sum1, 1);
    sum1 += __shfl_xor_sync(0xffffffffu, sum1, 2);
    const float inv0 = 1.f / sum0, inv1 = 1.f / sum1;

    // ---- store P (hi/lo) to smem, rows owned by this warp ----
    {
        const int g = lane >> 2, c2 = (lane & 3) * 2;
        const uint32_t r0off = (uint32_t)((w * 16 + g) * 272);
#pragma unroll
        for (int nt = 0; nt < 16; nt++) {
            uint32_t co = (uint32_t)((nt * 8 + c2) * 2);
            float v0 = acc[nt][0] * inv0, v1 = acc[nt][1] * inv0;
            float v2 = acc[nt][2] * inv1, v3 = acc[nt][3] * inv1;
            bf16 h0, l0, h1, l1;
            split1(v0, h0, l0); split1(v1, h1, l1);
            __nv_bfloat162 hh; hh.x = h0; hh.y = h1;
            __nv_bfloat162 ll; ll.x = l0; ll.y = l1;
            *(__nv_bfloat162*)(smem + r0off + co) = hh;
            *(__nv_bfloat162*)(smem + ATT_P_L + r0off + co) = ll;
            split1(v2, h0, l0); split1(v3, h1, l1);
            hh.x = h0; hh.y = h1; ll.x = l0; ll.y = l1;
            *(__nv_bfloat162*)(smem + r0off + 8 * 272 + co) = hh;
            *(__nv_bfloat162*)(smem + ATT_P_L + r0off + 8 * 272 + co) = ll;
            acc[nt][0] = acc[nt][1] = acc[nt][2] = acc[nt][3] = 0.f;
        }
    }
    __syncwarp();

    // ---- Phase 3: out = P * V (8 k-chunks) ----
    for (int v = 0; v < 8; v++) {
        CPWAIT2();
        __syncthreads();
        if (v + 3 < 8) loadV(v + 3);
        CPCOMMIT();

        const uint32_t ks = sb + ATT_KST + (uint32_t)((v & 3) * 8704);
        uint32_t ah[4], al[4];
        uint32_t pa = sb + wrow272 + (uint32_t)(v * 32) + aPL;
        ldsm4(ah, pa);
        ldsm4(al, pa + ATT_P_L);
#pragma unroll
        for (int g = 0; g < 8; g++) {
            uint32_t bh[4], bl[4];
            uint32_t baddr = ks + kr * 272 + (g * 16 + nf) * 2;
            ldsm4t(bh, baddr);
            ldsm4t(bl, baddr + 4352);
            mma_bf16(acc[2 * g],     ah, bh);
            mma_bf16(acc[2 * g],     ah, bl);
            mma_bf16(acc[2 * g],     al, bh);
            mma_bf16(acc[2 * g + 1], ah, bh + 2);
            mma_bf16(acc[2 * g + 1], ah, bl + 2);
            mma_bf16(acc[2 * g + 1], al, bh + 2);
        }
    }

    // ---- write att hi/lo planes ----
    {
        const int g = lane >> 2, c2 = (lane & 3) * 2;
        const size_t r0 = bhoff + (size_t)(w * 16 + g) * 128;
#pragma unroll
        for (int nt = 0; nt < 16; nt++) {
            int col = nt * 8 + c2;
            bf16 h0, l0, h1, l1;
            split1(acc[nt][0], h0, l0); split1(acc[nt][1], h1, l1);
            __nv_bfloat162 hh; hh.x = h0; hh.y = h1;
            __nv_bfloat162 ll; ll.x = l0; ll.y = l1;
            *(__nv_bfloat162*)(ath + r0 + col) = hh;
            *(__nv_bfloat162*)(atl + r0 + col) = ll;
            split1(acc[nt][2], h0, l0); split1(acc[nt][3], h1, l1);
            hh.x = h0; hh.y = h1; ll.x = l0; ll.y = l1;
            *(__nv_bfloat162*)(ath + r0 + 8 * 128 + col) = hh;
            *(__nv_bfloat162*)(atl + r0 + 8 * 128 + col) = ll;
        }
    }
}

// ======================= launch ==============================================
extern "C" void kernel_launch(void* const* d_in, const int* in_sizes, int n_in,
                              void* d_out, int out_size)
{
    (void)in_sizes; (void)n_in; (void)out_size;
    const float* inp[3] = { (const float*)d_in[0], (const float*)d_in[1],
                            (const float*)d_in[2] };
    const float* W[8] = { (const float*)d_in[3], (const float*)d_in[4],
                          (const float*)d_in[5], (const float*)d_in[6],
                          (const float*)d_in[7], (const float*)d_in[8],
                          (const float*)d_in[9], (const float*)d_in[10] };
    const float* bo = (const float*)d_in[11];
    float* out = (float*)d_out;

    void* symp = nullptr;
    cudaGetSymbolAddress(&symp, g_bf);
    bf16* P = (bf16*)symp;
    // plane pointers
    bf16* inh[3], *inl[3];
    for (int i = 0; i < 3; i++) { inh[i] = P + (2*i) * PLANE; inl[i] = P + (2*i+1) * PLANE; }
    bf16* oh[7], *ol[7];           // qw kw vw qp kp qc kc
    for (int i = 0; i < 7; i++) { oh[i] = P + (6 + 2*i) * PLANE; ol[i] = P + (7 + 2*i) * PLANE; }
    bf16* ath = P + 20 * PLANE, *atl = P + 21 * PLANE;
    bf16* wb = P + 22 * PLANE;
    bf16* wh[8], *wl[8];
    for (int i = 0; i < 8; i++) { wh[i] = wb + (2*i) * WPLANE; wl[i] = wb + (2*i+1) * WPLANE; }

    cudaFuncSetAttribute(gemm_bf, cudaFuncAttributeMaxDynamicSharedMemorySize, GEMM_SMEM);
    cudaFuncSetAttribute(attn_mma, cudaFuncAttributeMaxDynamicSharedMemorySize, ATT_SMEM);

    // 1) split inputs, transpose+split weights
    for (int i = 0; i < 3; i++)
        split_input<<<16384, 256>>>(inp[i], inh[i], inl[i]);
    dim3 tgrid(32, 32), tblk(32, 8);
    for (int i = 0; i < 8; i++)
        transpose_w_split<<<tgrid, tblk>>>(W[i], wh[i], wl[i]);

    // 2) projections -> hi/lo planes in head layout
    dim3 ggrid(8, 128), gblk(256);
    const int src[7] = { 0, 0, 0, 1, 1, 2, 2 };   // words, position, conscious
    for (int i = 0; i < 7; i++)
        gemm_bf<<<ggrid, gblk, GEMM_SMEM>>>(
            inh[src[i]], inl[src[i]], wh[i], wl[i],
            nullptr, oh[i], ol[i], nullptr, 128, 1024, 16384, 128);

    // 3) attention (qw kw | qp kp | qc kc, v) -> att planes
    attn_mma<<<1024, gblk, ATT_SMEM>>>(
        oh[0], ol[0], oh[1], ol[1],       // qw, kw
        oh[3], ol[3], oh[4], ol[4],       // qp, kp
        oh[5], ol[5], oh[6], ol[6],       // qc, kc
        oh[2], ol[2],                      // v
        ath, atl);

    // 4) final GEMM: att (head layout) * Wo^T + bias -> f32 out
    gemm_bf<<<ggrid, gblk, GEMM_SMEM>>>(
        ath, atl, wh[7], wl[7],
        out, nullptr, nullptr, bo, 16384, 128, 128, 1024);
}

// round 5
// speedup vs baseline: 2.4375x; 1.0045x over previous
#include <cuda_runtime.h>
#include <cuda_bf16.h>
#include <cstdint>

// Problem: B=128, N=128, D=1024, H=8, HD=128, M = B*N = 16384
#define PLANE  (16384ull * 1024ull)     // activation plane elems (bf16)
#define WPLANE (1024ull * 1024ull)      // weight plane elems (bf16)
// layout: inh(3) inl(3) ohb(7) olb(7) ath atl | whb(8) wlb(8)
__device__ __align__(1024) __nv_bfloat16 g_bf[22ull * PLANE + 16ull * WPLANE];

typedef __nv_bfloat16 bf16;

// ======================= PTX helpers =========================================
__device__ __forceinline__ uint32_t s2u(const void* p) {
    uint32_t a;
    asm("{ .reg .u64 t; cvta.to.shared.u64 t, %1; cvt.u32.u64 %0, t; }"
        : "=r"(a) : "l"(p));
    return a;
}
__device__ __forceinline__ void ldsm4(uint32_t* r, uint32_t addr) {
    asm volatile("ldmatrix.sync.aligned.m8n8.x4.shared.b16 {%0,%1,%2,%3}, [%4];"
                 : "=r"(r[0]), "=r"(r[1]), "=r"(r[2]), "=r"(r[3]) : "r"(addr));
}
__device__ __forceinline__ void ldsm4t(uint32_t* r, uint32_t addr) {
    asm volatile("ldmatrix.sync.aligned.m8n8.x4.trans.shared.b16 {%0,%1,%2,%3}, [%4];"
                 : "=r"(r[0]), "=r"(r[1]), "=r"(r[2]), "=r"(r[3]) : "r"(addr));
}
__device__ __forceinline__ void mma_bf16(float* d, const uint32_t* a, const uint32_t* b) {
    asm volatile(
        "mma.sync.aligned.m16n8k16.row.col.f32.bf16.bf16.f32 "
        "{%0,%1,%2,%3},{%4,%5,%6,%7},{%8,%9},{%0,%1,%2,%3};"
        : "+f"(d[0]), "+f"(d[1]), "+f"(d[2]), "+f"(d[3])
        : "r"(a[0]), "r"(a[1]), "r"(a[2]), "r"(a[3]), "r"(b[0]), "r"(b[1]));
}
#define CP16(dst, src) \
    asm volatile("cp.async.cg.shared.global [%0], [%1], 16;" :: "r"(dst), "l"(src))
#define CPCOMMIT() asm volatile("cp.async.commit_group;" ::: "memory")
#define CPWAIT2()  asm volatile("cp.async.wait_group 2;" ::: "memory")
#define CPWAIT0()  asm volatile("cp.async.wait_group 0;" ::: "memory")

__device__ __forceinline__ void split1(float v, bf16& h, bf16& l) {
    h = __float2bfloat16(v);
    l = __float2bfloat16(v - __bfloat162float(h));
}
__device__ __forceinline__ void packsplit2(float x0, float x1,
                                           uint32_t& hi, uint32_t& lo) {
    bf16 h0, l0, h1, l1;
    split1(x0, h0, l0); split1(x1, h1, l1);
    __nv_bfloat162 hh; hh.x = h0; hh.y = h1;
    __nv_bfloat162 ll; ll.x = l0; ll.y = l1;
    hi = *(uint32_t*)&hh; lo = *(uint32_t*)&ll;
}

// ======================= fused input split (3 inputs) ========================
__global__ __launch_bounds__(256) void split_all(
    const float* __restrict__ s0, const float* __restrict__ s1,
    const float* __restrict__ s2, bf16* __restrict__ hb, bf16* __restrict__ lb)
{
    const float* src = (blockIdx.y == 0) ? s0 : (blockIdx.y == 1) ? s1 : s2;
    bf16* h = hb + (size_t)blockIdx.y * PLANE;
    bf16* l = lb + (size_t)blockIdx.y * PLANE;
    size_t i4 = ((size_t)blockIdx.x * 256 + threadIdx.x) * 4;
    float4 v = *(const float4*)(src + i4);
    uint32_t hh0, ll0, hh1, ll1;
    packsplit2(v.x, v.y, hh0, ll0);
    packsplit2(v.z, v.w, hh1, ll1);
    *(uint32_t*)(h + i4)     = hh0; *(uint32_t*)(h + i4 + 2) = hh1;
    *(uint32_t*)(l + i4)     = ll0; *(uint32_t*)(l + i4 + 2) = ll1;
}

// ======================= fused weight transpose + split (4 weights) ==========
__global__ __launch_bounds__(256) void transpose4(
    const float* __restrict__ s0, const float* __restrict__ s1,
    const float* __restrict__ s2, const float* __restrict__ s3,
    bf16* __restrict__ hb, bf16* __restrict__ lb)
{
    const float* src = (blockIdx.z == 0) ? s0 : (blockIdx.z == 1) ? s1
                     : (blockIdx.z == 2) ? s2 : s3;
    bf16* h = hb + (size_t)blockIdx.z * WPLANE;
    bf16* l = lb + (size_t)blockIdx.z * WPLANE;
    __shared__ float t[32][33];
    int bx = blockIdx.x * 32, by = blockIdx.y * 32;
    int tx = threadIdx.x, ty = threadIdx.y;
#pragma unroll
    for (int i = ty; i < 32; i += 8)
        t[i][tx] = src[(size_t)(by + i) * 1024 + bx + tx];
    __syncthreads();
#pragma unroll
    for (int i = ty; i < 32; i += 8) {
        bf16 hh, ll;
        split1(t[tx][i], hh, ll);
        size_t o = (size_t)(bx + i) * 1024 + by + tx;
        h[o] = hh; l[o] = ll;
    }
}

// ======================= bf16-split mma.sync GEMM (cp.async, 4-stage) ========
// C = A * Bcat^T. Bcat = concatenated 1024x1024 transposed-weight planes.
// A idx(r,k) = (r/128)*131072 + (k/128)*ACB + (r%128)*ARI + (k%128)
// B plane = ct>>3; row in plane = (ct&7)*128 + r
// C (bf16): plane (ct>>3)*PLANE + (r/128)*131072 + (ct&7)*CCB + (r%128)*CRI + c
// C (f32, N=1024): plane 0, row-major via CCB/CRI.
#define GEMM_SMEM (4 * 24576)

__global__ __launch_bounds__(256, 2) void gemm_bf(
    const bf16* __restrict__ Ah, const bf16* __restrict__ Al,
    const bf16* __restrict__ Bh, const bf16* __restrict__ Bl,
    float* __restrict__ Cf, bf16* __restrict__ Ch, bf16* __restrict__ Cl,
    const float* __restrict__ bias, int ACB, int ARI, int CCB, int CRI)
{
    extern __shared__ __align__(1024) char smem[];
    const uint32_t sb = s2u(smem);
    const int tid = threadIdx.x;
    const int lane = tid & 31, wid = tid >> 5;
    const int rt = blockIdx.y, ct = blockIdx.x;
    const int bp = ct >> 3, bct = ct & 7;
    const int wm = wid & 1, wn = wid >> 1;
    const int s8 = lane >> 3, r8 = lane & 7;
    const uint32_t aLane = (uint32_t)(((s8 & 1) * 8 + r8) * 48 + (s8 >> 1) * 16);
    const uint32_t bLane = (uint32_t)(((s8 >> 1) * 8 + r8) * 48 + (s8 & 1) * 16);

    const int row = tid >> 1, half = tid & 1;
    const size_t aoff = (size_t)rt * 131072 + (size_t)row * ARI + half * 8;
    const size_t boff = (size_t)bp * WPLANE + (size_t)(bct * 128 + row) * 1024 + half * 8;
    const uint32_t dstoff = (uint32_t)(row * 48 + half * 16);

    float acc[4][4][4];
#pragma unroll
    for (int i = 0; i < 4; i++)
#pragma unroll
        for (int j = 0; j < 4; j++)
#pragma unroll
            for (int k = 0; k < 4; k++) acc[i][j][k] = 0.f;

    auto load_chunk = [&](int c) {
        const int kk = c * 16;
        const uint32_t st = sb + (uint32_t)((c & 3) * 24576) + dstoff;
        const size_t asrc = aoff + (size_t)(kk >> 7) * ACB + (kk & 127);
        const size_t bsrc = boff + kk;
        CP16(st,          Ah + asrc);
        CP16(st + 6144,   Al + asrc);
        CP16(st + 12288,  Bh + bsrc);
        CP16(st + 18432,  Bl + bsrc);
    };

    load_chunk(0); CPCOMMIT();
    load_chunk(1); CPCOMMIT();
    load_chunk(2); CPCOMMIT();

    for (int c = 0; c < 64; c++) {
        CPWAIT2();
        __syncthreads();
        if (c + 3 < 64) load_chunk(c + 3);
        CPCOMMIT();

        const uint32_t off = sb + (uint32_t)((c & 3) * 24576);
        uint32_t ah[4][4], bh[4][2], bl[4][2];
#pragma unroll
        for (int mt = 0; mt < 4; mt++)
            ldsm4(ah[mt], off + (uint32_t)((wm * 64 + mt * 16) * 48) + aLane);
#pragma unroll
        for (int g = 0; g < 2; g++) {
            uint32_t q[4];
            ldsm4(q, off + 12288u + (uint32_t)((wn * 32 + g * 16) * 48) + bLane);
            bh[g * 2][0] = q[0]; bh[g * 2][1] = q[1];
            bh[g * 2 + 1][0] = q[2]; bh[g * 2 + 1][1] = q[3];
            ldsm4(q, off + 18432u + (uint32_t)((wn * 32 + g * 16) * 48) + bLane);
            bl[g * 2][0] = q[0]; bl[g * 2][1] = q[1];
            bl[g * 2 + 1][0] = q[2]; bl[g * 2 + 1][1] = q[3];
        }
#pragma unroll
        for (int mt = 0; mt < 4; mt++)
#pragma unroll
            for (int nt = 0; nt < 4; nt++) {
                mma_bf16(acc[mt][nt], ah[mt], bh[nt]);
                mma_bf16(acc[mt][nt], ah[mt], bl[nt]);
            }
#pragma unroll
        for (int mt = 0; mt < 4; mt++) {
            uint32_t al[4];
            ldsm4(al, off + 6144u + (uint32_t)((wm * 64 + mt * 16) * 48) + aLane);
#pragma unroll
            for (int nt = 0; nt < 4; nt++)
                mma_bf16(acc[mt][nt], al, bh[nt]);
        }
    }

    // ---- epilogue ----
    const int g = lane >> 2, cp = (lane & 3) * 2;
    const size_t cbase = (size_t)bp * PLANE + (size_t)rt * 131072 + (size_t)bct * CCB;
#pragma unroll
    for (int mt = 0; mt < 4; mt++) {
#pragma unroll
        for (int nt = 0; nt < 4; nt++) {
            int r0 = wm * 64 + mt * 16 + g;
            int col = wn * 32 + nt * 8 + cp;
            float v0 = acc[mt][nt][0], v1 = acc[mt][nt][1];
            float v2 = acc[mt][nt][2], v3 = acc[mt][nt][3];
            size_t o0 = cbase + (size_t)r0 * CRI + col;
            size_t o1 = cbase + (size_t)(r0 + 8) * CRI + col;
            if (Cf) {
                float b0 = bias[ct * 128 + col], b1 = bias[ct * 128 + col + 1];
                *(float2*)(Cf + o0) = make_float2(v0 + b0, v1 + b1);
                *(float2*)(Cf + o1) = make_float2(v2 + b0, v3 + b1);
            } else {
                uint32_t hh, ll;
                packsplit2(v0, v1, hh, ll);
                *(uint32_t*)(Ch + o0) = hh; *(uint32_t*)(Cl + o0) = ll;
                packsplit2(v2, v3, hh, ll);
                *(uint32_t*)(Ch + o1) = hh; *(uint32_t*)(Cl + o1) = ll;
            }
        }
    }
}

// ======================= mma attention (register-resident P) =================
// One CTA per (b,h). Warp w owns rows w*16..w*16+15 (full 128 cols).
// sim = sum_s Q_s * K_s (plain 128x128 products), softmax rows, out = P * V.
// P never touches smem: sim C-fragments repack into bf16 hi/lo A-fragments.
// smem: Q stages@0 (4 x 12288: h@0 l@6144), K/V stages@49152 (4 x 8704).
#define ATT_SMEM 83968
#define ATT_KST  49152u

__global__ __launch_bounds__(256, 1) void attn_mma(
    const bf16* __restrict__ ohb, const bf16* __restrict__ olb,
    bf16* __restrict__ ath, bf16* __restrict__ atl)
{
    extern __shared__ __align__(1024) char smem[];
    const uint32_t sb = s2u(smem);
    const int tid = threadIdx.x;
    const int lane = tid & 31, w = tid >> 5;
    const size_t bhoff = (size_t)blockIdx.x * 16384;

    // plane order in ohb: 0 qw, 1 kw, 2 vw, 3 qp, 4 kp, 5 qc, 6 kc
    const int qpl[3] = { 0, 3, 5 }, kpl[3] = { 1, 4, 6 };

    const int s8 = lane >> 3, r8 = lane & 7;
    const uint32_t aLane = (uint32_t)(((s8 & 1) * 8 + r8) * 48 + (s8 >> 1) * 16);
    const uint32_t kr = (uint32_t)(lane & 15);
    const uint32_t nf = (uint32_t)((lane >> 4) * 8);
    const uint32_t wrow48 = (uint32_t)(w * 16 * 48);

    const int qrow = tid >> 1, qhalf = tid & 1;
    const uint32_t qdst = (uint32_t)(qrow * 48 + qhalf * 16);
    const int krow = tid >> 4, kseg = tid & 15;
    const uint32_t kdst = (uint32_t)(krow * 272 + kseg * 16);

    auto loadQK = [&](int it) {
        int s = it >> 3, c = it & 7;
        uint32_t qs = sb + (uint32_t)((it & 3) * 12288) + qdst;
        size_t qsrc = (size_t)qpl[s] * PLANE + bhoff + (size_t)qrow * 128 + c * 16 + qhalf * 8;
        CP16(qs,        ohb + qsrc);
        CP16(qs + 6144, olb + qsrc);
        uint32_t ks = sb + ATT_KST + (uint32_t)((it & 3) * 8704) + kdst;
        size_t ksrc = (size_t)kpl[s] * PLANE + bhoff + (size_t)(c * 16 + krow) * 128 + kseg * 8;
        CP16(ks,        ohb + ksrc);
        CP16(ks + 4352, olb + ksrc);
    };
    auto loadV = [&](int v) {
        uint32_t ks = sb + ATT_KST + (uint32_t)((v & 3) * 8704) + kdst;
        size_t ksrc = 2ull * PLANE + bhoff + (size_t)(v * 16 + krow) * 128 + kseg * 8;
        CP16(ks,        ohb + ksrc);
        CP16(ks + 4352, olb + ksrc);
    };

    float acc[16][4];
#pragma unroll
    for (int i = 0; i < 16; i++)
#pragma unroll
        for (int j = 0; j < 4; j++) acc[i][j] = 0.f;

    loadQK(0); CPCOMMIT();
    loadQK(1); CPCOMMIT();
    loadQK(2); CPCOMMIT();

    // ---- Phase 1: sim (24 iters = 3 streams x 8 k-chunks) ----
    for (int it = 0; it < 24; it++) {
        CPWAIT2();
        __syncthreads();
        if (it + 3 < 24) loadQK(it + 3);
        CPCOMMIT();

        const uint32_t qs = sb + (uint32_t)((it & 3) * 12288);
        const uint32_t ks = sb + ATT_KST + (uint32_t)((it & 3) * 8704);
        uint32_t ah[4], al[4];
        ldsm4(ah, qs + wrow48 + aLane);
        ldsm4(al, qs + 6144 + wrow48 + aLane);
#pragma unroll
        for (int g = 0; g < 8; g++) {
            uint32_t bh[4], bl[4];
            uint32_t baddr = ks + kr * 272 + (g * 16 + nf) * 2;
            ldsm4t(bh, baddr);
            ldsm4t(bl, baddr + 4352);
            mma_bf16(acc[2 * g],     ah, bh);
            mma_bf16(acc[2 * g],     ah, bl);
            mma_bf16(acc[2 * g],     al, bh);
            mma_bf16(acc[2 * g + 1], ah, bh + 2);
            mma_bf16(acc[2 * g + 1], ah, bl + 2);
            mma_bf16(acc[2 * g + 1], al, bh + 2);
        }
    }

    // drain QK traffic, then prefetch V into stages 0..2 (overlaps softmax)
    CPWAIT0();
    __syncthreads();
    loadV(0); CPCOMMIT();
    loadV(1); CPCOMMIT();
    loadV(2); CPCOMMIT();

    // ---- Phase 2: softmax (warp-local; lane rows g and g+8) ----
    const float SC = 0.08838834764831845f;   // 128^-0.5
    float m0 = -1e30f, m1 = -1e30f;
#pragma unroll
    for (int nt = 0; nt < 16; nt++) {
#pragma unroll
        for (int j = 0; j < 4; j++) acc[nt][j] *= SC;
        m0 = fmaxf(m0, fmaxf(acc[nt][0], acc[nt][1]));
        m1 = fmaxf(m1, fmaxf(acc[nt][2], acc[nt][3]));
    }
    m0 = fmaxf(m0, __shfl_xor_sync(0xffffffffu, m0, 1));
    m0 = fmaxf(m0, __shfl_xor_sync(0xffffffffu, m0, 2));
    m1 = fmaxf(m1, __shfl_xor_sync(0xffffffffu, m1, 1));
    m1 = fmaxf(m1, __shfl_xor_sync(0xffffffffu, m1, 2));
    float sum0 = 0.f, sum1 = 0.f;
#pragma unroll
    for (int nt = 0; nt < 16; nt++) {
        acc[nt][0] = __expf(acc[nt][0] - m0); sum0 += acc[nt][0];
        acc[nt][1] = __expf(acc[nt][1] - m0); sum0 += acc[nt][1];
        acc[nt][2] = __expf(acc[nt][2] - m1); sum1 += acc[nt][2];
        acc[nt][3] = __expf(acc[nt][3] - m1); sum1 += acc[nt][3];
    }
    sum0 += __shfl_xor_sync(0xffffffffu, sum0, 1);
    sum0 += __shfl_xor_sync(0xffffffffu, sum0, 2);
    sum1 += __shfl_xor_sync(0xffffffffu, sum1, 1);
    sum1 += __shfl_xor_sync(0xffffffffu, sum1, 2);
    const float inv0 = 1.f / sum0, inv1 = 1.f / sum1;

    // ---- repack P into A-fragments (C-frag layout == A-frag layout) ----
    // k16 chunk c uses n8 tiles 2c (k0-7) and 2c+1 (k8-15):
    //  a0=(g,k0-7)  a1=(g+8,k0-7)  a2=(g,k8-15)  a3=(g+8,k8-15)
    uint32_t ph[8][4], pl[8][4];
#pragma unroll
    for (int c = 0; c < 8; c++) {
        packsplit2(acc[2*c][0]   * inv0, acc[2*c][1]   * inv0, ph[c][0], pl[c][0]);
        packsplit2(acc[2*c][2]   * inv1, acc[2*c][3]   * inv1, ph[c][1], pl[c][1]);
        packsplit2(acc[2*c+1][0] * inv0, acc[2*c+1][1] * inv0, ph[c][2], pl[c][2]);
        packsplit2(acc[2*c+1][2] * inv1, acc[2*c+1][3] * inv1, ph[c][3], pl[c][3]);
    }
#pragma unroll
    for (int i = 0; i < 16; i++)
#pragma unroll
        for (int j = 0; j < 4; j++) acc[i][j] = 0.f;

    // ---- Phase 3: out = P * V (8 k-chunks) ----
    for (int v = 0; v < 8; v++) {
        CPWAIT2();
        __syncthreads();
        if (v + 3 < 8) loadV(v + 3);
        CPCOMMIT();

        const uint32_t ks = sb + ATT_KST + (uint32_t)((v & 3) * 8704);
#pragma unroll
        for (int g = 0; g < 8; g++) {
            uint32_t bh[4], bl[4];
            uint32_t baddr = ks + kr * 272 + (g * 16 + nf) * 2;
            ldsm4t(bh, baddr);
            ldsm4t(bl, baddr + 4352);
            mma_bf16(acc[2 * g],     ph[v], bh);
            mma_bf16(acc[2 * g],     ph[v], bl);
            mma_bf16(acc[2 * g],     pl[v], bh);
            mma_bf16(acc[2 * g + 1], ph[v], bh + 2);
            mma_bf16(acc[2 * g + 1], ph[v], bl + 2);
            mma_bf16(acc[2 * g + 1], pl[v], bh + 2);
        }
    }

    // ---- write att hi/lo planes ----
    {
        const int g = lane >> 2, c2 = (lane & 3) * 2;
        const size_t r0 = bhoff + (size_t)(w * 16 + g) * 128;
#pragma unroll
        for (int nt = 0; nt < 16; nt++) {
            int col = nt * 8 + c2;
            uint32_t hh, ll;
            packsplit2(acc[nt][0], acc[nt][1], hh, ll);
            *(uint32_t*)(ath + r0 + col) = hh;
            *(uint32_t*)(atl + r0 + col) = ll;
            packsplit2(acc[nt][2], acc[nt][3], hh, ll);
            *(uint32_t*)(ath + r0 + 8 * 128 + col) = hh;
            *(uint32_t*)(atl + r0 + 8 * 128 + col) = ll;
        }
    }
}

// ======================= launch ==============================================
extern "C" void kernel_launch(void* const* d_in, const int* in_sizes, int n_in,
                              void* d_out, int out_size)
{
    (void)in_sizes; (void)n_in; (void)out_size;
    const float* inp[3] = { (const float*)d_in[0], (const float*)d_in[1],
                            (const float*)d_in[2] };
    const float* W[8] = { (const float*)d_in[3], (const float*)d_in[4],
                          (const float*)d_in[5], (const float*)d_in[6],
                          (const float*)d_in[7], (const float*)d_in[8],
                          (const float*)d_in[9], (const float*)d_in[10] };
    const float* bo = (const float*)d_in[11];
    float* out = (float*)d_out;

    void* symp = nullptr;
    cudaGetSymbolAddress(&symp, g_bf);
    bf16* P = (bf16*)symp;
    bf16* inh = P;                      // 3 planes
    bf16* inl = P + 3ull * PLANE;       // 3 planes
    bf16* ohb = P + 6ull * PLANE;       // 7 planes: qw kw vw qp kp qc kc
    bf16* olb = P + 13ull * PLANE;      // 7 planes
    bf16* ath = P + 20ull * PLANE;
    bf16* atl = P + 21ull * PLANE;
    bf16* whb = P + 22ull * PLANE;      // 8 weight h planes
    bf16* wlb = whb + 8ull * WPLANE;    // 8 weight l planes

    cudaFuncSetAttribute(gemm_bf, cudaFuncAttributeMaxDynamicSharedMemorySize, GEMM_SMEM);
    cudaFuncSetAttribute(attn_mma, cudaFuncAttributeMaxDynamicSharedMemorySize, ATT_SMEM);

    // 0) split inputs (one launch)
    split_all<<<dim3(16384, 3), 256>>>(inp[0], inp[1], inp[2], inh, inl);

    // 1-2) transpose+split weights (two launches of 4)
    dim3 tgrid(32, 32, 4), tblk(32, 8);
    transpose4<<<tgrid, tblk>>>(W[0], W[1], W[2], W[3], whb, wlb);
    transpose4<<<tgrid, tblk>>>(W[4], W[5], W[6], W[7],
                                whb + 4ull * WPLANE, wlb + 4ull * WPLANE);

    // 3-5) combined projections -> hi/lo planes in head layout
    dim3 gblk(256);
    gemm_bf<<<dim3(24, 128), gblk, GEMM_SMEM>>>(
        inh, inl, whb, wlb,
        nullptr, ohb, olb, nullptr, 128, 1024, 16384, 128);                 // words: q,k,v
    gemm_bf<<<dim3(16, 128), gblk, GEMM_SMEM>>>(
        inh + PLANE, inl + PLANE, whb + 3ull * WPLANE, wlb + 3ull * WPLANE,
        nullptr, ohb + 3ull * PLANE, olb + 3ull * PLANE, nullptr,
        128, 1024, 16384, 128);                                             // position: q,k
    gemm_bf<<<dim3(16, 128), gblk, GEMM_SMEM>>>(
        inh + 2ull * PLANE, inl + 2ull * PLANE,
        whb + 5ull * WPLANE, wlb + 5ull * WPLANE,
        nullptr, ohb + 5ull * PLANE, olb + 5ull * PLANE, nullptr,
        128, 1024, 16384, 128);                                             // conscious: q,k

    // 6) attention -> att planes
    attn_mma<<<1024, gblk, ATT_SMEM>>>(ohb, olb, ath, atl);

    // 7) final GEMM: att * Wo^T + bias -> f32 out (row-major)
    gemm_bf<<<dim3(8, 128), gblk, GEMM_SMEM>>>(
        ath, atl, whb + 7ull * WPLANE, wlb + 7ull * WPLANE,
        out, nullptr, nullptr, bo, 16384, 128, 128, 1024);
}